// round 4
// baseline (speedup 1.0000x reference)
#include <cuda_runtime.h>
#include <math.h>

#define B_    4096
#define INF   64
#define KM    16
#define SQ    32
#define HH    64
#define NMD   48
#define NH    512
#define NT    1024
#define PMAXF 8.0f

#define ROWS  16          // batch rows per block
#define RSTR  20          // transposed smem stride (16 rows + 4 pad), 80B (16B-aligned)

// Scratch (no allocations allowed)
__device__ float g_tab[KM * NT];   // G_k(p) tables

// ---------------------------------------------------------------------------
// f32x2 helpers (Blackwell packed fp32 SIMD2)
// ---------------------------------------------------------------------------
__device__ __forceinline__ unsigned long long pack2(float lo, float hi) {
    unsigned long long r;
    asm("mov.b64 %0, {%1, %2};" : "=l"(r) : "f"(lo), "f"(hi));
    return r;
}
__device__ __forceinline__ float2 unpack2(unsigned long long v) {
    float2 r;
    asm("mov.b64 {%0, %1}, %2;" : "=f"(r.x), "=f"(r.y) : "l"(v));
    return r;
}
__device__ __forceinline__ void fma2(unsigned long long& d,
                                     unsigned long long a,
                                     unsigned long long b) {
    asm("fma.rn.f32x2 %0, %1, %2, %0;" : "+l"(d) : "l"(a), "l"(b));
}

// ---------------------------------------------------------------------------
// Kernel 1: tabulate G_k(p). 4 threads per entry (j-loop split 4-way).
// 256 blocks x 256 threads: block = 64 entries of one k.
// ---------------------------------------------------------------------------
__global__ void __launch_bounds__(256) build_tab_kernel(
    const float* __restrict__ mw1, const float* __restrict__ mb1,
    const float* __restrict__ mw2, const float* __restrict__ mb2,
    const float* __restrict__ mw3, const float* __restrict__ mb3)
{
    __shared__ float s_w2[HH * HH];
    __shared__ float s_w1[HH], s_b1[HH], s_b2[HH], s_w3[HH];

    int k     = blockIdx.x >> 4;                 // 16 blocks per k
    int entry = (blockIdx.x & 15) * 64 + (threadIdx.x >> 2);
    int jq    = threadIdx.x & 3;                 // j-quadrant 0..3

    {
        const float4* src = (const float4*)(mw2 + k * HH * HH);
        float4* dst = (float4*)s_w2;
        for (int idx = threadIdx.x; idx < HH * HH / 4; idx += 256)
            dst[idx] = src[idx];
    }
    if (threadIdx.x < HH) {
        s_w1[threadIdx.x] = mw1[k * HH + threadIdx.x];
        s_b1[threadIdx.x] = mb1[k * HH + threadIdx.x];
        s_b2[threadIdx.x] = mb2[k * HH + threadIdx.x];
        s_w3[threadIdx.x] = mw3[k * HH + threadIdx.x];
    }
    __syncthreads();

    float p = -PMAXF + (2.f * PMAXF / (NT - 1)) * (float)entry;

    float h1v[HH];
#pragma unroll
    for (int h = 0; h < HH; h++)
        h1v[h] = tanhf(fmaf(p, s_w1[h], s_b1[h]));

    float z = 0.f;
#pragma unroll
    for (int jg = 0; jg < 4; jg++) {
        int j0 = jq * 16 + jg * 4;
        float4 acc = *(const float4*)&s_b2[j0];
#pragma unroll
        for (int h = 0; h < HH; h++) {
            float4 w = *(const float4*)&s_w2[h * HH + j0];
            float a = h1v[h];
            acc.x = fmaf(a, w.x, acc.x);
            acc.y = fmaf(a, w.y, acc.y);
            acc.z = fmaf(a, w.z, acc.z);
            acc.w = fmaf(a, w.w, acc.w);
        }
        z = fmaf(s_w3[j0 + 0], tanhf(acc.x), z);
        z = fmaf(s_w3[j0 + 1], tanhf(acc.y), z);
        z = fmaf(s_w3[j0 + 2], tanhf(acc.z), z);
        z = fmaf(s_w3[j0 + 3], tanhf(acc.w), z);
    }
    // combine the 4 j-quadrants (width-4 shuffle groups == same entry)
    z += __shfl_down_sync(0xffffffffu, z, 2, 4);
    z += __shfl_down_sync(0xffffffffu, z, 1, 4);
    if (jq == 0) {
        z += __ldg(mb3 + k);
        g_tab[k * NT + entry] = fmaxf(z, 0.f) + log1pf(expf(-fabsf(z)));
    }
}

// ---------------------------------------------------------------------------
// Kernel 2: fused mono-lookup + 3-layer MLP + output.
// Block = 16 rows, 256 threads (8 warps), 2 blocks/SM.
// Layer 2: warp = (row-half rh = warp>>2) x (col-group cg = warp&3).
// Lane owns 4 cols x 8 rows -> per i: 2 LDS.128 + 1 LDG.128 per 32 fma2.
// ---------------------------------------------------------------------------
__global__ void __launch_bounds__(256, 2) fused_kernel(
    const float* __restrict__ X,    const float* __restrict__ wlin,
    const float* __restrict__ w1,   const float* __restrict__ b1,
    const float* __restrict__ w2,   const float* __restrict__ b2,
    const float* __restrict__ w3,   const float* __restrict__ b3,
    float* __restrict__ out)
{
    extern __shared__ float sm[];
    float* xs     = sm;                            // [NMD][RSTR]  transposed x_nm
    float* a1s    = xs + NMD * RSTR;               // [NH][RSTR]   transposed a1
    float* wpart  = a1s + NH * RSTR;               // [8][8]       per-warp row partials
    float* mono_s = wpart + 8 * 8;                 // [ROWS]

    const int tid  = threadIdx.x;
    const int warp = tid >> 5;
    const int lane = tid & 31;
    const int b0   = blockIdx.x * ROWS;

    // ---- stage x_nm transposed: xs[i][r] ----
    for (int idx = tid; idx < ROWS * NMD; idx += 256) {
        int r = idx / NMD, i = idx % NMD;
        xs[i * RSTR + r] = X[(b0 + r) * INF + KM + i];
    }

    // ---- mono term: one (row, k) per thread, width-16 shuffle reduce ----
    {
        int r = tid >> 4;          // 0..15
        int k = tid & 15;          // 0..15
        const float scale = (float)(NT - 1) / (2.f * PMAXF);
        float x = __ldg(X + (b0 + r) * INF + k);
        const float* tk = g_tab + k * NT;
        float acc = 0.f;
#pragma unroll
        for (int s = 0; s < SQ; s++) {
            float t = (float)s * (1.f / (SQ - 1));
            float f = (x * t + PMAXF) * scale;
            f = fminf(fmaxf(f, 0.f), (float)(NT - 1) - 1e-3f);
            int i0 = (int)f;
            float fr = f - (float)i0;
            float g0 = tk[i0];
            float g1 = tk[i0 + 1];
            acc += fmaf(fr, g1 - g0, g0);
        }
        float part = acc * (1.f / SQ) * x * __ldg(wlin + k);
#pragma unroll
        for (int off = 8; off; off >>= 1)
            part += __shfl_down_sync(0xffffffffu, part, off, 16);
        if ((tid & 15) == 0) mono_s[r] = part;
    }
    __syncthreads();

    // ---- layer 1: lane owns 2 cols x 16 rows (8 warps cover 512 cols) ----
    {
        const int c0 = warp * 64 + lane * 2;
        unsigned long long acc[8][2];
#pragma unroll
        for (int rp = 0; rp < 8; rp++) { acc[rp][0] = 0ull; acc[rp][1] = 0ull; }

        const float* wp = w1 + c0;
        float2 wbuf[2][8];
#pragma unroll
        for (int u = 0; u < 8; u++) wbuf[0][u] = *(const float2*)(wp + u * NH);

#pragma unroll 2
        for (int c = 0; c < NMD / 8; c++) {
            int cur = c & 1, nxt = cur ^ 1;
            if (c + 1 < NMD / 8) {
                const float* wn = wp + (c + 1) * 8 * NH;
#pragma unroll
                for (int u = 0; u < 8; u++) wbuf[nxt][u] = *(const float2*)(wn + u * NH);
            }
            const float* abase = xs + c * 8 * RSTR;
#pragma unroll
            for (int u = 0; u < 8; u++) {
                unsigned long long wd0 = pack2(wbuf[cur][u].x, wbuf[cur][u].x);
                unsigned long long wd1 = pack2(wbuf[cur][u].y, wbuf[cur][u].y);
                const ulonglong2* ap = (const ulonglong2*)(abase + u * RSTR);
#pragma unroll
                for (int q = 0; q < 4; q++) {
                    ulonglong2 a = ap[q];
                    fma2(acc[2 * q][0],     a.x, wd0);
                    fma2(acc[2 * q][1],     a.x, wd1);
                    fma2(acc[2 * q + 1][0], a.y, wd0);
                    fma2(acc[2 * q + 1][1], a.y, wd1);
                }
            }
        }
        float2 bv = *(const float2*)(b1 + c0);
#pragma unroll
        for (int rp = 0; rp < 8; rp++) {
            float2 v0 = unpack2(acc[rp][0]);
            float2 v1 = unpack2(acc[rp][1]);
            float2 s0, s1;
            s0.x = fmaxf(v0.x + bv.x, 0.f);
            s0.y = fmaxf(v0.y + bv.x, 0.f);
            s1.x = fmaxf(v1.x + bv.y, 0.f);
            s1.y = fmaxf(v1.y + bv.y, 0.f);
            *(float2*)(a1s + c0 * RSTR + 2 * rp)       = s0;
            *(float2*)(a1s + (c0 + 1) * RSTR + 2 * rp) = s1;
        }
    }
    __syncthreads();

    // ---- layer 2 (+ fused layer-3 dot): lane owns 4 cols x 8 rows ----
    {
        const int rh = warp >> 2;              // row-half: rows rh*8 .. rh*8+7
        const int cg = warp & 3;               // col-group
        const int c0 = cg * 128 + lane * 4;    // this lane's 4 output cols

        unsigned long long acc[4][4];          // [row-pair][col]
#pragma unroll
        for (int rp = 0; rp < 4; rp++)
#pragma unroll
            for (int cc = 0; cc < 4; cc++) acc[rp][cc] = 0ull;

        const float* wp = w2 + c0;
        float4 wbuf[2][4];
#pragma unroll
        for (int u = 0; u < 4; u++) wbuf[0][u] = *(const float4*)(wp + u * NH);

        for (int c = 0; c < NH / 4; c++) {
            int cur = c & 1, nxt = cur ^ 1;
            int cn = (c + 1 < NH / 4) ? (c + 1) : c;   // clamp (re-read last chunk)
            const float* wn = wp + cn * 4 * NH;
#pragma unroll
            for (int u = 0; u < 4; u++) wbuf[nxt][u] = *(const float4*)(wn + u * NH);

            const float* abase = a1s + c * 4 * RSTR + rh * 8;
#pragma unroll
            for (int u = 0; u < 4; u++) {
                float4 wv = wbuf[cur][u];
                unsigned long long wd0 = pack2(wv.x, wv.x);
                unsigned long long wd1 = pack2(wv.y, wv.y);
                unsigned long long wd2 = pack2(wv.z, wv.z);
                unsigned long long wd3 = pack2(wv.w, wv.w);
                const ulonglong2* ap = (const ulonglong2*)(abase + u * RSTR);
                ulonglong2 a01 = ap[0];        // rows 0-3 of this half
                ulonglong2 a23 = ap[1];        // rows 4-7
                fma2(acc[0][0], a01.x, wd0); fma2(acc[0][1], a01.x, wd1);
                fma2(acc[0][2], a01.x, wd2); fma2(acc[0][3], a01.x, wd3);
                fma2(acc[1][0], a01.y, wd0); fma2(acc[1][1], a01.y, wd1);
                fma2(acc[1][2], a01.y, wd2); fma2(acc[1][3], a01.y, wd3);
                fma2(acc[2][0], a23.x, wd0); fma2(acc[2][1], a23.x, wd1);
                fma2(acc[2][2], a23.x, wd2); fma2(acc[2][3], a23.x, wd3);
                fma2(acc[3][0], a23.y, wd0); fma2(acc[3][1], a23.y, wd1);
                fma2(acc[3][2], a23.y, wd2); fma2(acc[3][3], a23.y, wd3);
            }
        }

        // epilogue: relu(acc + b2) . w3 -> per-row partial for this 128-col slice
        float4 b2v = *(const float4*)(b2 + c0);
        float4 w3v = *(const float4*)(w3 + c0);
#pragma unroll
        for (int rp = 0; rp < 4; rp++) {
            float2 v0 = unpack2(acc[rp][0]);
            float2 v1 = unpack2(acc[rp][1]);
            float2 v2 = unpack2(acc[rp][2]);
            float2 v3 = unpack2(acc[rp][3]);
            float plo = fmaxf(v0.x + b2v.x, 0.f) * w3v.x;
            plo = fmaf(fmaxf(v1.x + b2v.y, 0.f), w3v.y, plo);
            plo = fmaf(fmaxf(v2.x + b2v.z, 0.f), w3v.z, plo);
            plo = fmaf(fmaxf(v3.x + b2v.w, 0.f), w3v.w, plo);
            float phi = fmaxf(v0.y + b2v.x, 0.f) * w3v.x;
            phi = fmaf(fmaxf(v1.y + b2v.y, 0.f), w3v.y, phi);
            phi = fmaf(fmaxf(v2.y + b2v.z, 0.f), w3v.z, phi);
            phi = fmaf(fmaxf(v3.y + b2v.w, 0.f), w3v.w, phi);
#pragma unroll
            for (int off = 16; off; off >>= 1) {
                plo += __shfl_down_sync(0xffffffffu, plo, off);
                phi += __shfl_down_sync(0xffffffffu, phi, off);
            }
            if (lane == 0) {
                wpart[warp * 8 + 2 * rp]     = plo;   // local rows 2rp, 2rp+1
                wpart[warp * 8 + 2 * rp + 1] = phi;
            }
        }
    }
    __syncthreads();

    // ---- final: sum 4 col-group slices of this row's half + bias + mono ----
    if (tid < ROWS) {
        int rh = tid >> 3, rl = tid & 7;
        float s = 0.f;
#pragma unroll
        for (int cg = 0; cg < 4; cg++)
            s += wpart[(rh * 4 + cg) * 8 + rl];
        out[b0 + tid] = s + __ldg(b3) + mono_s[tid];
    }
}

// ---------------------------------------------------------------------------
extern "C" void kernel_launch(void* const* d_in, const int* in_sizes, int n_in,
                              void* d_out, int out_size)
{
    const float* x    = (const float*)d_in[0];
    const float* mw1  = (const float*)d_in[1];
    const float* mb1  = (const float*)d_in[2];
    const float* mw2  = (const float*)d_in[3];
    const float* mb2  = (const float*)d_in[4];
    const float* mw3  = (const float*)d_in[5];
    const float* mb3  = (const float*)d_in[6];
    const float* wlin = (const float*)d_in[7];
    const float* nw1  = (const float*)d_in[8];
    const float* nb1  = (const float*)d_in[9];
    const float* nw2  = (const float*)d_in[10];
    const float* nb2  = (const float*)d_in[11];
    const float* nw3  = (const float*)d_in[12];
    const float* nb3  = (const float*)d_in[13];
    float* out = (float*)d_out;

    int smem = (NMD * RSTR + NH * RSTR + 8 * 8 + ROWS) * (int)sizeof(float);  // ~45.1 KB
    cudaFuncSetAttribute(fused_kernel, cudaFuncAttributeMaxDynamicSharedMemorySize, smem);

    build_tab_kernel<<<KM * 16, 256>>>(mw1, mb1, mw2, mb2, mw3, mb3);
    fused_kernel<<<B_ / ROWS, 256, smem>>>(x, wlin, nw1, nb1, nw2, nb2, nw3, nb3, out);
}

// round 6
// speedup vs baseline: 1.0078x; 1.0078x over previous
#include <cuda_runtime.h>
#include <math.h>

#define B_    4096
#define INF   64
#define KM    16
#define SQ    32
#define HH    64
#define NMD   48
#define NH    512
#define NT    1024
#define PMAXF 8.0f

#define ROWS  16          // batch rows per block
#define RSTR  20          // transposed smem stride (16 rows + 4 pad), 80B (16B-aligned)
#define KSTR  36          // ksum slot stride in floats: 144B, 16B-aligned, conflict-free

// Scratch (no allocations allowed)
__device__ float g_tab[KM * NT];   // G_k(p) tables

// ---------------------------------------------------------------------------
// f32x2 helpers (Blackwell packed fp32 SIMD2)
// ---------------------------------------------------------------------------
__device__ __forceinline__ unsigned long long pack2(float lo, float hi) {
    unsigned long long r;
    asm("mov.b64 %0, {%1, %2};" : "=l"(r) : "f"(lo), "f"(hi));
    return r;
}
__device__ __forceinline__ float2 unpack2(unsigned long long v) {
    float2 r;
    asm("mov.b64 {%0, %1}, %2;" : "=f"(r.x), "=f"(r.y) : "l"(v));
    return r;
}
__device__ __forceinline__ void fma2(unsigned long long& d,
                                     unsigned long long a,
                                     unsigned long long b) {
    asm("fma.rn.f32x2 %0, %1, %2, %0;" : "+l"(d) : "l"(a), "l"(b));
}
__device__ __forceinline__ void add2(unsigned long long& d, unsigned long long a) {
    asm("add.rn.f32x2 %0, %0, %1;" : "+l"(d) : "l"(a));
}

// ---------------------------------------------------------------------------
// Kernel 1: tabulate G_k(p). 128 blocks (8 per k) x 128 threads. (R3 version)
// ---------------------------------------------------------------------------
__global__ void __launch_bounds__(128) build_tab_kernel(
    const float* __restrict__ mw1, const float* __restrict__ mb1,
    const float* __restrict__ mw2, const float* __restrict__ mb2,
    const float* __restrict__ mw3, const float* __restrict__ mb3)
{
    __shared__ float s_w2[HH * HH];
    __shared__ float s_w1[HH], s_b1[HH], s_b2[HH], s_w3[HH];

    int k = blockIdx.x >> 3;
    int i = (blockIdx.x & 7) * 128 + threadIdx.x;   // 0..NT-1

    {
        const float4* src = (const float4*)(mw2 + k * HH * HH);
        float4* dst = (float4*)s_w2;
        for (int idx = threadIdx.x; idx < HH * HH / 4; idx += 128)
            dst[idx] = src[idx];
    }
    if (threadIdx.x < HH) {
        s_w1[threadIdx.x] = mw1[k * HH + threadIdx.x];
        s_b1[threadIdx.x] = mb1[k * HH + threadIdx.x];
        s_b2[threadIdx.x] = mb2[k * HH + threadIdx.x];
        s_w3[threadIdx.x] = mw3[k * HH + threadIdx.x];
    }
    __syncthreads();

    float p = -PMAXF + (2.f * PMAXF / (NT - 1)) * (float)i;

    float h1v[HH];
#pragma unroll
    for (int h = 0; h < HH; h++)
        h1v[h] = tanhf(fmaf(p, s_w1[h], s_b1[h]));

    float z = __ldg(mb3 + k);
#pragma unroll 2
    for (int jg = 0; jg < HH / 4; jg++) {
        float4 acc = *(const float4*)&s_b2[jg * 4];
#pragma unroll
        for (int h = 0; h < HH; h++) {
            float4 w = *(const float4*)&s_w2[h * HH + jg * 4];
            float a = h1v[h];
            acc.x = fmaf(a, w.x, acc.x);
            acc.y = fmaf(a, w.y, acc.y);
            acc.z = fmaf(a, w.z, acc.z);
            acc.w = fmaf(a, w.w, acc.w);
        }
        z = fmaf(s_w3[jg * 4 + 0], tanhf(acc.x), z);
        z = fmaf(s_w3[jg * 4 + 1], tanhf(acc.y), z);
        z = fmaf(s_w3[jg * 4 + 2], tanhf(acc.z), z);
        z = fmaf(s_w3[jg * 4 + 3], tanhf(acc.w), z);
    }
    float g = fmaxf(z, 0.f) + log1pf(expf(-fabsf(z)));
    g_tab[k * NT + i] = g;
}

// ---------------------------------------------------------------------------
// Kernel 2: fused mono-lookup + 3-layer MLP + output.
// Block = 16 rows, 512 threads (16 warps), 2 blocks/SM (regs capped at 64).
// Layer 2 K-SPLIT: warp = (kh = warp>>3) x (rh = (warp>>2)&1) x (cg = warp&3).
// Each warp: 256 i, lane owns 4 cols x 8 rows. K-halves combined in smem
// (packed f32x2 adds) before relu.
// ---------------------------------------------------------------------------
__global__ void __launch_bounds__(512, 2) fused_kernel(
    const float* __restrict__ X,    const float* __restrict__ wlin,
    const float* __restrict__ w1,   const float* __restrict__ b1,
    const float* __restrict__ w2,   const float* __restrict__ b2,
    const float* __restrict__ w3,   const float* __restrict__ b3,
    float* __restrict__ out)
{
    extern __shared__ float sm[];
    float* xs     = sm;                            // [NMD][RSTR]
    float* a1s    = xs + NMD * RSTR;               // [NH][RSTR]
    float* ksum   = a1s + NH * RSTR;               // [256][KSTR] K-split partials
    float* wpart  = ksum + 256 * KSTR;             // [8][8]
    float* mono_s = wpart + 8 * 8;                 // [ROWS]

    const int tid  = threadIdx.x;
    const int warp = tid >> 5;
    const int lane = tid & 31;
    const int b0   = blockIdx.x * ROWS;

    // ---- stage x_nm transposed: xs[i][r] ----
    for (int idx = tid; idx < ROWS * NMD; idx += 512) {
        int r = idx / NMD, i = idx % NMD;
        xs[i * RSTR + r] = X[(b0 + r) * INF + KM + i];
    }

    // ---- mono term: threads 0..255, one (row, k) each ----
    if (tid < 256) {
        int r = tid >> 4;
        int k = tid & 15;
        const float scale = (float)(NT - 1) / (2.f * PMAXF);
        float x = __ldg(X + (b0 + r) * INF + k);
        const float* tk = g_tab + k * NT;
        float acc = 0.f;
#pragma unroll
        for (int s = 0; s < SQ; s++) {
            float t = (float)s * (1.f / (SQ - 1));
            float f = (x * t + PMAXF) * scale;
            f = fminf(fmaxf(f, 0.f), (float)(NT - 1) - 1e-3f);
            int i0 = (int)f;
            float fr = f - (float)i0;
            float g0 = tk[i0];
            float g1 = tk[i0 + 1];
            acc += fmaf(fr, g1 - g0, g0);
        }
        float part = acc * (1.f / SQ) * x * __ldg(wlin + k);
#pragma unroll
        for (int off = 8; off; off >>= 1)
            part += __shfl_down_sync(0xffffffffu, part, off, 16);
        if ((tid & 15) == 0) mono_s[r] = part;
    }
    __syncthreads();

    // ---- layer 1: 16 warps x 32 cols; lane owns 1 col x 16 rows ----
    {
        const int c = warp * 32 + lane;
        unsigned long long acc[8];
#pragma unroll
        for (int rp = 0; rp < 8; rp++) acc[rp] = 0ull;

        const float* wp = w1 + c;
#pragma unroll 4
        for (int i = 0; i < NMD; i++) {
            float wv = wp[i * NH];
            unsigned long long wd = pack2(wv, wv);
            const ulonglong2* ap = (const ulonglong2*)(xs + i * RSTR);
#pragma unroll
            for (int q = 0; q < 4; q++) {
                ulonglong2 a = ap[q];
                fma2(acc[2 * q],     a.x, wd);
                fma2(acc[2 * q + 1], a.y, wd);
            }
        }
        float bv = b1[c];
#pragma unroll
        for (int rp = 0; rp < 8; rp++) {
            float2 v = unpack2(acc[rp]);
            float2 s;
            s.x = fmaxf(v.x + bv, 0.f);
            s.y = fmaxf(v.y + bv, 0.f);
            *(float2*)(a1s + c * RSTR + 2 * rp) = s;
        }
    }
    __syncthreads();

    // ---- layer 2 (K-split) + fused layer-3 dot ----
    {
        const int kh = warp >> 3;              // K-half: i in [kh*256, kh*256+256)
        const int wl = warp & 7;
        const int rh = wl >> 2;                // row-half: rows rh*8..rh*8+7
        const int cg = wl & 3;
        const int c0 = cg * 128 + lane * 4;    // this lane's 4 output cols

        unsigned long long acc[4][4];          // [row-pair][col]
#pragma unroll
        for (int rp = 0; rp < 4; rp++)
#pragma unroll
            for (int cc = 0; cc < 4; cc++) acc[rp][cc] = 0ull;

        const float* wp = w2 + (kh * 256) * NH + c0;
        float4 wbuf[2][2];
        wbuf[0][0] = *(const float4*)(wp);
        wbuf[0][1] = *(const float4*)(wp + NH);

#pragma unroll 2
        for (int c = 0; c < 128; c++) {        // 128 chunks of 2 i
            int cur = c & 1, nxt = cur ^ 1;
            int cn = (c < 127) ? (c + 1) : c;
            const float* wn = wp + cn * 2 * NH;
            wbuf[nxt][0] = *(const float4*)(wn);
            wbuf[nxt][1] = *(const float4*)(wn + NH);

            const float* abase = a1s + (kh * 256 + c * 2) * RSTR + rh * 8;
#pragma unroll
            for (int u = 0; u < 2; u++) {
                float4 wv = wbuf[cur][u];
                unsigned long long wd0 = pack2(wv.x, wv.x);
                unsigned long long wd1 = pack2(wv.y, wv.y);
                unsigned long long wd2 = pack2(wv.z, wv.z);
                unsigned long long wd3 = pack2(wv.w, wv.w);
                const ulonglong2* ap = (const ulonglong2*)(abase + u * RSTR);
                ulonglong2 a01 = ap[0];
                ulonglong2 a23 = ap[1];
                fma2(acc[0][0], a01.x, wd0); fma2(acc[0][1], a01.x, wd1);
                fma2(acc[0][2], a01.x, wd2); fma2(acc[0][3], a01.x, wd3);
                fma2(acc[1][0], a01.y, wd0); fma2(acc[1][1], a01.y, wd1);
                fma2(acc[1][2], a01.y, wd2); fma2(acc[1][3], a01.y, wd3);
                fma2(acc[2][0], a23.x, wd0); fma2(acc[2][1], a23.x, wd1);
                fma2(acc[2][2], a23.x, wd2); fma2(acc[2][3], a23.x, wd3);
                fma2(acc[3][0], a23.y, wd0); fma2(acc[3][1], a23.y, wd1);
                fma2(acc[3][2], a23.y, wd2); fma2(acc[3][3], a23.y, wd3);
            }
        }

        // K-half 1 publishes its partials
        float* slot = ksum + (wl * 32 + lane) * KSTR;
        if (kh == 1) {
#pragma unroll
            for (int rp = 0; rp < 4; rp++) {
                ulonglong2 v0; v0.x = acc[rp][0]; v0.y = acc[rp][1];
                ulonglong2 v1; v1.x = acc[rp][2]; v1.y = acc[rp][3];
                *(ulonglong2*)(slot + rp * 8)     = v0;
                *(ulonglong2*)(slot + rp * 8 + 4) = v1;
            }
        }
        __syncthreads();

        if (kh == 0) {
            // combine K-halves (packed adds)
#pragma unroll
            for (int rp = 0; rp < 4; rp++) {
                ulonglong2 v0 = *(const ulonglong2*)(slot + rp * 8);
                ulonglong2 v1 = *(const ulonglong2*)(slot + rp * 8 + 4);
                add2(acc[rp][0], v0.x); add2(acc[rp][1], v0.y);
                add2(acc[rp][2], v1.x); add2(acc[rp][3], v1.y);
            }

            // epilogue: relu(acc + b2) . w3 -> per-row partials
            float4 b2v = *(const float4*)(b2 + c0);
            float4 w3v = *(const float4*)(w3 + c0);
#pragma unroll
            for (int rp = 0; rp < 4; rp++) {
                float2 v0 = unpack2(acc[rp][0]);
                float2 v1 = unpack2(acc[rp][1]);
                float2 v2 = unpack2(acc[rp][2]);
                float2 v3 = unpack2(acc[rp][3]);
                float plo = fmaxf(v0.x + b2v.x, 0.f) * w3v.x;
                plo = fmaf(fmaxf(v1.x + b2v.y, 0.f), w3v.y, plo);
                plo = fmaf(fmaxf(v2.x + b2v.z, 0.f), w3v.z, plo);
                plo = fmaf(fmaxf(v3.x + b2v.w, 0.f), w3v.w, plo);
                float phi = fmaxf(v0.y + b2v.x, 0.f) * w3v.x;
                phi = fmaf(fmaxf(v1.y + b2v.y, 0.f), w3v.y, phi);
                phi = fmaf(fmaxf(v2.y + b2v.z, 0.f), w3v.z, phi);
                phi = fmaf(fmaxf(v3.y + b2v.w, 0.f), w3v.w, phi);
#pragma unroll
                for (int off = 16; off; off >>= 1) {
                    plo += __shfl_down_sync(0xffffffffu, plo, off);
                    phi += __shfl_down_sync(0xffffffffu, phi, off);
                }
                if (lane == 0) {
                    wpart[wl * 8 + 2 * rp]     = plo;
                    wpart[wl * 8 + 2 * rp + 1] = phi;
                }
            }
        }
    }
    __syncthreads();

    // ---- final: sum 4 col-group slices of this row's half + bias + mono ----
    if (tid < ROWS) {
        int rh = tid >> 3, rl = tid & 7;
        float s = 0.f;
#pragma unroll
        for (int cg = 0; cg < 4; cg++)
            s += wpart[(rh * 4 + cg) * 8 + rl];
        out[b0 + tid] = s + __ldg(b3) + mono_s[tid];
    }
}

// ---------------------------------------------------------------------------
extern "C" void kernel_launch(void* const* d_in, const int* in_sizes, int n_in,
                              void* d_out, int out_size)
{
    const float* x    = (const float*)d_in[0];
    const float* mw1  = (const float*)d_in[1];
    const float* mb1  = (const float*)d_in[2];
    const float* mw2  = (const float*)d_in[3];
    const float* mb2  = (const float*)d_in[4];
    const float* mw3  = (const float*)d_in[5];
    const float* mb3  = (const float*)d_in[6];
    const float* wlin = (const float*)d_in[7];
    const float* nw1  = (const float*)d_in[8];
    const float* nb1  = (const float*)d_in[9];
    const float* nw2  = (const float*)d_in[10];
    const float* nb2  = (const float*)d_in[11];
    const float* nw3  = (const float*)d_in[12];
    const float* nb3  = (const float*)d_in[13];
    float* out = (float*)d_out;

    int smem = (NMD * RSTR + NH * RSTR + 256 * KSTR + 8 * 8 + ROWS) * (int)sizeof(float);
    cudaFuncSetAttribute(fused_kernel, cudaFuncAttributeMaxDynamicSharedMemorySize, smem);

    build_tab_kernel<<<KM * 8, 128>>>(mw1, mb1, mw2, mb2, mw3, mb3);
    fused_kernel<<<B_ / ROWS, 512, smem>>>(x, wlin, nw1, nb1, nw2, nb2, nw3, nb3, out);
}

// round 7
// speedup vs baseline: 1.4588x; 1.4475x over previous
#include <cuda_runtime.h>
#include <cuda_bf16.h>
#include <math.h>

#define B_    4096
#define INF   64
#define KM    16
#define SQ    32
#define HH    64
#define NMD   48
#define NH    512
#define NT    1024
#define PMAXF 8.0f

#define ROWS  32          // batch rows per block
#define RSTR  36          // xs transposed stride (32 rows + 4 pad)
#define ASTR  520         // a1 bf16 row stride (520*2B = 1040B: 16B-aligned, ldmatrix conflict-free)

// Scratch (no allocations allowed)
__device__ float g_tab[KM * NT];                 // G_k(p) tables
__device__ __nv_bfloat16 w2h_frag[NH * NH];      // w2 hi, MMA B-fragment order
__device__ __nv_bfloat16 w2l_frag[NH * NH];      // w2 lo, MMA B-fragment order

// ---------------------------------------------------------------------------
// helpers
// ---------------------------------------------------------------------------
__device__ __forceinline__ unsigned long long pack2(float lo, float hi) {
    unsigned long long r;
    asm("mov.b64 %0, {%1, %2};" : "=l"(r) : "f"(lo), "f"(hi));
    return r;
}
__device__ __forceinline__ float2 unpack2(unsigned long long v) {
    float2 r;
    asm("mov.b64 {%0, %1}, %2;" : "=f"(r.x), "=f"(r.y) : "l"(v));
    return r;
}
__device__ __forceinline__ void fma2(unsigned long long& d,
                                     unsigned long long a,
                                     unsigned long long b) {
    asm("fma.rn.f32x2 %0, %1, %2, %0;" : "+l"(d) : "l"(a), "l"(b));
}
__device__ __forceinline__ unsigned smem_u32(const void* p) {
    unsigned r;
    asm("{ .reg .u64 t; cvta.to.shared.u64 t, %1; cvt.u32.u64 %0, t; }"
        : "=r"(r) : "l"(p));
    return r;
}
__device__ __forceinline__ void ldsm_x4(unsigned& r0, unsigned& r1,
                                        unsigned& r2, unsigned& r3, unsigned addr) {
    asm volatile("ldmatrix.sync.aligned.m8n8.x4.shared.b16 {%0,%1,%2,%3}, [%4];"
                 : "=r"(r0), "=r"(r1), "=r"(r2), "=r"(r3) : "r"(addr));
}
__device__ __forceinline__ void mma_bf16(float* c, const unsigned* a, const unsigned* b) {
    asm volatile(
        "mma.sync.aligned.m16n8k16.row.col.f32.bf16.bf16.f32 "
        "{%0,%1,%2,%3}, {%4,%5,%6,%7}, {%8,%9}, {%0,%1,%2,%3};"
        : "+f"(c[0]), "+f"(c[1]), "+f"(c[2]), "+f"(c[3])
        : "r"(a[0]), "r"(a[1]), "r"(a[2]), "r"(a[3]), "r"(b[0]), "r"(b[1]));
}

// ---------------------------------------------------------------------------
// Kernel 0: split w2 into bf16 hi/lo in per-lane MMA B-fragment order.
// B frag (m16n8k16, col-major k16 x n8): lane l: b0={B[(l%4)*2][l/4],B[(l%4)*2+1][l/4]},
// b1 = same k+8. Storage: 4 bf16 per (nf,kf,lane): slot=((nf*32+kf)*32+lane)*4.
// ---------------------------------------------------------------------------
__global__ void __launch_bounds__(512) prep_kernel(const float* __restrict__ w2)
{
    int idx = blockIdx.x * 512 + threadIdx.x;   // 512*512 elements
    int i = idx >> 9;        // k (row of w2)
    int j = idx & 511;       // n (col of w2)
    float v = w2[idx];
    __nv_bfloat16 h = __float2bfloat16(v);
    __nv_bfloat16 l = __float2bfloat16(v - __bfloat162float(h));
    int nf = j >> 3, n_in = j & 7;
    int kf = i >> 4, k_in = i & 15;
    int reg  = k_in >> 3;
    int elem = k_in & 1;
    int lane = n_in * 4 + ((k_in & 7) >> 1);
    int fidx = ((((nf * 32) + kf) * 32 + lane) * 2 + reg) * 2 + elem;
    w2h_frag[fidx] = h;
    w2l_frag[fidx] = l;
}

// ---------------------------------------------------------------------------
// Kernel 1: tabulate G_k(p). 128 blocks (8 per k) x 128 threads. (known good)
// ---------------------------------------------------------------------------
__global__ void __launch_bounds__(128) build_tab_kernel(
    const float* __restrict__ mw1, const float* __restrict__ mb1,
    const float* __restrict__ mw2, const float* __restrict__ mb2,
    const float* __restrict__ mw3, const float* __restrict__ mb3)
{
    __shared__ float s_w2[HH * HH];
    __shared__ float s_w1[HH], s_b1[HH], s_b2[HH], s_w3[HH];

    int k = blockIdx.x >> 3;
    int i = (blockIdx.x & 7) * 128 + threadIdx.x;

    {
        const float4* src = (const float4*)(mw2 + k * HH * HH);
        float4* dst = (float4*)s_w2;
        for (int idx = threadIdx.x; idx < HH * HH / 4; idx += 128)
            dst[idx] = src[idx];
    }
    if (threadIdx.x < HH) {
        s_w1[threadIdx.x] = mw1[k * HH + threadIdx.x];
        s_b1[threadIdx.x] = mb1[k * HH + threadIdx.x];
        s_b2[threadIdx.x] = mb2[k * HH + threadIdx.x];
        s_w3[threadIdx.x] = mw3[k * HH + threadIdx.x];
    }
    __syncthreads();

    float p = -PMAXF + (2.f * PMAXF / (NT - 1)) * (float)i;

    float h1v[HH];
#pragma unroll
    for (int h = 0; h < HH; h++)
        h1v[h] = tanhf(fmaf(p, s_w1[h], s_b1[h]));

    float z = __ldg(mb3 + k);
#pragma unroll 2
    for (int jg = 0; jg < HH / 4; jg++) {
        float4 acc = *(const float4*)&s_b2[jg * 4];
#pragma unroll
        for (int h = 0; h < HH; h++) {
            float4 w = *(const float4*)&s_w2[h * HH + jg * 4];
            float a = h1v[h];
            acc.x = fmaf(a, w.x, acc.x);
            acc.y = fmaf(a, w.y, acc.y);
            acc.z = fmaf(a, w.z, acc.z);
            acc.w = fmaf(a, w.w, acc.w);
        }
        z = fmaf(s_w3[jg * 4 + 0], tanhf(acc.x), z);
        z = fmaf(s_w3[jg * 4 + 1], tanhf(acc.y), z);
        z = fmaf(s_w3[jg * 4 + 2], tanhf(acc.z), z);
        z = fmaf(s_w3[jg * 4 + 3], tanhf(acc.w), z);
    }
    float g = fmaxf(z, 0.f) + log1pf(expf(-fabsf(z)));
    g_tab[k * NT + i] = g;
}

// ---------------------------------------------------------------------------
// Kernel 2: fused mono-lookup + layer1(scalar) + layer2(MMA split-bf16) + out.
// Block = 32 rows, 512 threads (16 warps), grid 128.
// Warp w owns cols [w*32, w*32+32): per kf: 4 ldmatrix.x4 + 8 LDG.64 + 24 mma.
// ---------------------------------------------------------------------------
__global__ void __launch_bounds__(512) fused_kernel(
    const float* __restrict__ X,  const float* __restrict__ wlin,
    const float* __restrict__ w1, const float* __restrict__ b1,
    const float* __restrict__ b2, const float* __restrict__ w3,
    const float* __restrict__ b3, float* __restrict__ out)
{
    extern __shared__ float sm[];
    float* xs     = sm;                          // [NMD][RSTR]
    float* wpart  = xs + NMD * RSTR;             // [16][32]
    float* mono_s = wpart + 16 * 32;             // [32]
    __nv_bfloat16* a1h = (__nv_bfloat16*)(mono_s + 32);   // [32][ASTR]
    __nv_bfloat16* a1l = a1h + ROWS * ASTR;               // [32][ASTR]

    const int tid  = threadIdx.x;
    const int warp = tid >> 5;
    const int lane = tid & 31;
    const int b0   = blockIdx.x * ROWS;

    // ---- stage x_nm transposed: xs[i][r] ----
    for (int idx = tid; idx < ROWS * NMD; idx += 512) {
        int r = idx / NMD, i = idx % NMD;
        xs[i * RSTR + r] = X[(b0 + r) * INF + KM + i];
    }

    // ---- mono term: one (row, k) per thread, width-16 shuffle reduce ----
    {
        int r = tid >> 4;          // 0..31
        int k = tid & 15;
        const float scale = (float)(NT - 1) / (2.f * PMAXF);
        float x = __ldg(X + (b0 + r) * INF + k);
        const float* tk = g_tab + k * NT;
        float acc = 0.f;
#pragma unroll
        for (int s = 0; s < SQ; s++) {
            float t = (float)s * (1.f / (SQ - 1));
            float f = (x * t + PMAXF) * scale;
            f = fminf(fmaxf(f, 0.f), (float)(NT - 1) - 1e-3f);
            int i0 = (int)f;
            float fr = f - (float)i0;
            float g0 = tk[i0];
            float g1 = tk[i0 + 1];
            acc += fmaf(fr, g1 - g0, g0);
        }
        float part = acc * (1.f / SQ) * x * __ldg(wlin + k);
#pragma unroll
        for (int off = 8; off; off >>= 1)
            part += __shfl_down_sync(0xffffffffu, part, off, 16);
        if ((tid & 15) == 0) mono_s[r] = part;
    }
    __syncthreads();

    // ---- layer 1: thread owns col c = tid, all 32 rows; relu + bf16 hi/lo ----
    {
        const int c = tid;
        unsigned long long acc[16];
#pragma unroll
        for (int rp = 0; rp < 16; rp++) acc[rp] = 0ull;

        const float* wp = w1 + c;
#pragma unroll 4
        for (int i = 0; i < NMD; i++) {
            float wv = wp[i * NH];
            unsigned long long wd = pack2(wv, wv);
            const ulonglong2* ap = (const ulonglong2*)(xs + i * RSTR);
#pragma unroll
            for (int q = 0; q < 8; q++) {
                ulonglong2 a = ap[q];
                fma2(acc[2 * q],     a.x, wd);
                fma2(acc[2 * q + 1], a.y, wd);
            }
        }
        float bv = b1[c];
#pragma unroll
        for (int rp = 0; rp < 16; rp++) {
            float2 v = unpack2(acc[rp]);
            float s0 = fmaxf(v.x + bv, 0.f);
            float s1 = fmaxf(v.y + bv, 0.f);
            __nv_bfloat16 h0 = __float2bfloat16(s0);
            __nv_bfloat16 h1 = __float2bfloat16(s1);
            a1h[(2 * rp) * ASTR + c]     = h0;
            a1h[(2 * rp + 1) * ASTR + c] = h1;
            a1l[(2 * rp) * ASTR + c]     = __float2bfloat16(s0 - __bfloat162float(h0));
            a1l[(2 * rp + 1) * ASTR + c] = __float2bfloat16(s1 - __bfloat162float(h1));
        }
    }
    __syncthreads();

    // ---- layer 2: split-bf16 MMA, warp owns 32 cols x 32 rows ----
    {
        float acc[2][4][4];
#pragma unroll
        for (int m = 0; m < 2; m++)
#pragma unroll
            for (int nf = 0; nf < 4; nf++)
#pragma unroll
                for (int e = 0; e < 4; e++) acc[m][nf][e] = 0.f;

        const unsigned a1h_u = smem_u32(a1h);
        const unsigned a1l_u = smem_u32(a1l);
        const int arow  = lane & 15;
        const int acol8 = (lane >> 4) * 8;

        uint2 bh[2][4], bl[2][4];
#pragma unroll
        for (int nf = 0; nf < 4; nf++) {
            int slot = ((warp * 4 + nf) * 32 + 0) * 32 + lane;
            bh[0][nf] = *(const uint2*)(w2h_frag + slot * 4);
            bl[0][nf] = *(const uint2*)(w2l_frag + slot * 4);
        }

        for (int kf = 0; kf < 32; kf++) {
            int cur = kf & 1, nxt = cur ^ 1;
            if (kf < 31) {
#pragma unroll
                for (int nf = 0; nf < 4; nf++) {
                    int slot = ((warp * 4 + nf) * 32 + (kf + 1)) * 32 + lane;
                    bh[nxt][nf] = *(const uint2*)(w2h_frag + slot * 4);
                    bl[nxt][nf] = *(const uint2*)(w2l_frag + slot * 4);
                }
            }
            unsigned ah[2][4], al[2][4];
#pragma unroll
            for (int m = 0; m < 2; m++) {
                unsigned off = ((m * 16 + arow) * ASTR + kf * 16 + acol8) * 2;
                ldsm_x4(ah[m][0], ah[m][1], ah[m][2], ah[m][3], a1h_u + off);
                ldsm_x4(al[m][0], al[m][1], al[m][2], al[m][3], a1l_u + off);
            }
#pragma unroll
            for (int m = 0; m < 2; m++)
#pragma unroll
                for (int nf = 0; nf < 4; nf++) {
                    mma_bf16(acc[m][nf], ah[m], (const unsigned*)&bh[cur][nf]);
                    mma_bf16(acc[m][nf], ah[m], (const unsigned*)&bl[cur][nf]);
                    mma_bf16(acc[m][nf], al[m], (const unsigned*)&bh[cur][nf]);
                }
        }

        // epilogue: relu(acc + b2) . w3 -> per-row partials (32-col slice)
#pragma unroll
        for (int m = 0; m < 2; m++) {
            float p0 = 0.f, p1 = 0.f;
#pragma unroll
            for (int nf = 0; nf < 4; nf++) {
                int col = warp * 32 + nf * 8 + (lane & 3) * 2;
                float2 b2v = *(const float2*)(b2 + col);
                float2 w3v = *(const float2*)(w3 + col);
                p0 = fmaf(fmaxf(acc[m][nf][0] + b2v.x, 0.f), w3v.x, p0);
                p0 = fmaf(fmaxf(acc[m][nf][1] + b2v.y, 0.f), w3v.y, p0);
                p1 = fmaf(fmaxf(acc[m][nf][2] + b2v.x, 0.f), w3v.x, p1);
                p1 = fmaf(fmaxf(acc[m][nf][3] + b2v.y, 0.f), w3v.y, p1);
            }
            p0 += __shfl_xor_sync(0xffffffffu, p0, 1);
            p0 += __shfl_xor_sync(0xffffffffu, p0, 2);
            p1 += __shfl_xor_sync(0xffffffffu, p1, 1);
            p1 += __shfl_xor_sync(0xffffffffu, p1, 2);
            if ((lane & 3) == 0) {
                int r0 = m * 16 + (lane >> 2);
                wpart[warp * 32 + r0]     = p0;   // rows r0, r0+8 of D
                wpart[warp * 32 + r0 + 8] = p1;
            }
        }
    }
    __syncthreads();

    // ---- final: sum 16 warp slices + bias + mono ----
    if (tid < ROWS) {
        float s = 0.f;
#pragma unroll
        for (int w = 0; w < 16; w++) s += wpart[w * 32 + tid];
        out[b0 + tid] = s + __ldg(b3) + mono_s[tid];
    }
}

// ---------------------------------------------------------------------------
extern "C" void kernel_launch(void* const* d_in, const int* in_sizes, int n_in,
                              void* d_out, int out_size)
{
    const float* x    = (const float*)d_in[0];
    const float* mw1  = (const float*)d_in[1];
    const float* mb1  = (const float*)d_in[2];
    const float* mw2  = (const float*)d_in[3];
    const float* mb2  = (const float*)d_in[4];
    const float* mw3  = (const float*)d_in[5];
    const float* mb3  = (const float*)d_in[6];
    const float* wlin = (const float*)d_in[7];
    const float* nw1  = (const float*)d_in[8];
    const float* nb1  = (const float*)d_in[9];
    const float* nw2  = (const float*)d_in[10];
    const float* nb2  = (const float*)d_in[11];
    const float* nw3  = (const float*)d_in[12];
    const float* nb3  = (const float*)d_in[13];
    float* out = (float*)d_out;

    // smem: xs + wpart + mono + a1h + a1l
    int smem = (NMD * RSTR + 16 * 32 + 32) * (int)sizeof(float)
             + 2 * ROWS * ASTR * (int)sizeof(__nv_bfloat16);   // 75648 B
    cudaFuncSetAttribute(fused_kernel, cudaFuncAttributeMaxDynamicSharedMemorySize, smem);

    prep_kernel<<<NH * NH / 512, 512>>>(nw2);
    build_tab_kernel<<<KM * 8, 128>>>(mw1, mb1, mw2, mb2, mw3, mb3);
    fused_kernel<<<B_ / ROWS, 512, smem>>>(x, wlin, nw1, nb1, nb2, nw3, nb3, out);
}

// round 8
// speedup vs baseline: 1.5659x; 1.0734x over previous
#include <cuda_runtime.h>
#include <cuda_fp16.h>
#include <math.h>

#define B_    4096
#define INF   64
#define KM    16
#define SQ    32
#define HH    64
#define NMD   48
#define NH    512
#define NT    1024
#define PMAXF 8.0f

#define ROWS  32          // batch rows per block
#define RSTR  36          // xs transposed stride (32 rows + 4 pad)
#define ASTR  520         // a1 fp16 row stride (1040B: 16B-aligned, ldmatrix conflict-free)

// Scratch (no allocations allowed)
__device__ float g_tab[KM * NT];                          // G_k(p) tables
__device__ __align__(16) __half w2f_frag[NH * NH];        // w2 fp16, MMA B-fragment order

// ---------------------------------------------------------------------------
// helpers
// ---------------------------------------------------------------------------
__device__ __forceinline__ unsigned long long pack2(float lo, float hi) {
    unsigned long long r;
    asm("mov.b64 %0, {%1, %2};" : "=l"(r) : "f"(lo), "f"(hi));
    return r;
}
__device__ __forceinline__ float2 unpack2(unsigned long long v) {
    float2 r;
    asm("mov.b64 {%0, %1}, %2;" : "=f"(r.x), "=f"(r.y) : "l"(v));
    return r;
}
__device__ __forceinline__ void fma2(unsigned long long& d,
                                     unsigned long long a,
                                     unsigned long long b) {
    asm("fma.rn.f32x2 %0, %1, %2, %0;" : "+l"(d) : "l"(a), "l"(b));
}
__device__ __forceinline__ unsigned smem_u32(const void* p) {
    unsigned r;
    asm("{ .reg .u64 t; cvta.to.shared.u64 t, %1; cvt.u32.u64 %0, t; }"
        : "=r"(r) : "l"(p));
    return r;
}
__device__ __forceinline__ void ldsm_x4(unsigned& r0, unsigned& r1,
                                        unsigned& r2, unsigned& r3, unsigned addr) {
    asm volatile("ldmatrix.sync.aligned.m8n8.x4.shared.b16 {%0,%1,%2,%3}, [%4];"
                 : "=r"(r0), "=r"(r1), "=r"(r2), "=r"(r3) : "r"(addr));
}
__device__ __forceinline__ void mma_f16(float* c, const unsigned* a, const unsigned* b) {
    asm volatile(
        "mma.sync.aligned.m16n8k16.row.col.f32.f16.f16.f32 "
        "{%0,%1,%2,%3}, {%4,%5,%6,%7}, {%8,%9}, {%0,%1,%2,%3};"
        : "+f"(c[0]), "+f"(c[1]), "+f"(c[2]), "+f"(c[3])
        : "r"(a[0]), "r"(a[1]), "r"(a[2]), "r"(a[3]), "r"(b[0]), "r"(b[1]));
}

// ---------------------------------------------------------------------------
// Kernel 0: convert w2 to fp16 in per-lane MMA B-fragment order.
// Slot (kf, lane, nf) holds 4 halves [b0.lo, b0.hi, b1.lo, b1.hi].
// Layout: uint2 index = (kf*32 + lane)*64 + nf  ->  lane's 4 n-frags of one
// warp are 32 contiguous bytes (2x LDG.128 in the mainloop).
// One thread per slot; stores fully coalesced.
// ---------------------------------------------------------------------------
__global__ void __launch_bounds__(256) prep_kernel(const float* __restrict__ w2)
{
    int t    = blockIdx.x * 256 + threadIdx.x;   // 65536 slots
    int nf   = t & 63;
    int lane = (t >> 6) & 31;
    int kf   = t >> 11;

    int j     = nf * 8 + (lane >> 2);
    int kbase = kf * 16 + (lane & 3) * 2;

    float v00 = __ldg(w2 + (kbase + 0) * NH + j);
    float v01 = __ldg(w2 + (kbase + 1) * NH + j);
    float v10 = __ldg(w2 + (kbase + 8) * NH + j);
    float v11 = __ldg(w2 + (kbase + 9) * NH + j);

    __half2 b0 = __floats2half2_rn(v00, v01);   // .x (low) = elem0
    __half2 b1 = __floats2half2_rn(v10, v11);

    uint2 st;
    st.x = *(unsigned*)&b0;
    st.y = *(unsigned*)&b1;
    ((uint2*)w2f_frag)[(kf * 32 + lane) * 64 + nf] = st;
}

// ---------------------------------------------------------------------------
// Kernel 1: tabulate G_k(p). 128 blocks x 256 threads, 2 threads per entry
// (j-dim split in half; tanh h1v duplicated 2x only). f32x2 inner loop.
// ---------------------------------------------------------------------------
__global__ void __launch_bounds__(256) build_tab_kernel(
    const float* __restrict__ mw1, const float* __restrict__ mb1,
    const float* __restrict__ mw2, const float* __restrict__ mb2,
    const float* __restrict__ mw3, const float* __restrict__ mb3)
{
    __shared__ float s_w2[HH * HH];
    __shared__ float s_w1[HH], s_b1[HH], s_b2[HH], s_w3[HH];

    int k  = blockIdx.x >> 3;                       // 8 blocks per k
    int i  = (blockIdx.x & 7) * 128 + (threadIdx.x >> 1);
    int jh = threadIdx.x & 1;                       // j-half

    {
        const float4* src = (const float4*)(mw2 + k * HH * HH);
        float4* dst = (float4*)s_w2;
        for (int idx = threadIdx.x; idx < HH * HH / 4; idx += 256)
            dst[idx] = src[idx];
    }
    if (threadIdx.x < HH) {
        s_w1[threadIdx.x] = mw1[k * HH + threadIdx.x];
        s_b1[threadIdx.x] = mb1[k * HH + threadIdx.x];
        s_b2[threadIdx.x] = mb2[k * HH + threadIdx.x];
        s_w3[threadIdx.x] = mw3[k * HH + threadIdx.x];
    }
    __syncthreads();

    float p = -PMAXF + (2.f * PMAXF / (NT - 1)) * (float)i;

    float h1v[HH];
#pragma unroll
    for (int h = 0; h < HH; h++)
        h1v[h] = tanhf(fmaf(p, s_w1[h], s_b1[h]));

    float z = 0.f;
#pragma unroll 2
    for (int jg = 0; jg < 8; jg++) {
        int j0 = jh * 32 + jg * 4;
        unsigned long long accA = pack2(s_b2[j0],     s_b2[j0 + 1]);
        unsigned long long accB = pack2(s_b2[j0 + 2], s_b2[j0 + 3]);
#pragma unroll
        for (int h = 0; h < HH; h++) {
            const ulonglong2* wv = (const ulonglong2*)&s_w2[h * HH + j0];
            ulonglong2 w = *wv;
            unsigned long long ad = pack2(h1v[h], h1v[h]);
            fma2(accA, w.x, ad);
            fma2(accB, w.y, ad);
        }
        float2 va = unpack2(accA);
        float2 vb = unpack2(accB);
        z = fmaf(s_w3[j0 + 0], tanhf(va.x), z);
        z = fmaf(s_w3[j0 + 1], tanhf(va.y), z);
        z = fmaf(s_w3[j0 + 2], tanhf(vb.x), z);
        z = fmaf(s_w3[j0 + 3], tanhf(vb.y), z);
    }
    z += __shfl_down_sync(0xffffffffu, z, 1, 2);
    if (jh == 0) {
        z += __ldg(mb3 + k);
        g_tab[k * NT + i] = fmaxf(z, 0.f) + log1pf(expf(-fabsf(z)));
    }
}

// ---------------------------------------------------------------------------
// Kernel 2: fused mono-lookup + layer1(scalar f32) + layer2(single-fp16 MMA)
// Block = 32 rows, 512 threads (16 warps), grid 128.
// Warp w owns cols [w*32, w*32+32): per kf: 2 ldmatrix.x4 + 2 LDG.128 + 8 mma.
// ---------------------------------------------------------------------------
__global__ void __launch_bounds__(512) fused_kernel(
    const float* __restrict__ X,  const float* __restrict__ wlin,
    const float* __restrict__ w1, const float* __restrict__ b1,
    const float* __restrict__ b2, const float* __restrict__ w3,
    const float* __restrict__ b3, float* __restrict__ out)
{
    extern __shared__ float sm[];
    float* xs     = sm;                          // [NMD][RSTR]
    float* wpart  = xs + NMD * RSTR;             // [16][32]
    float* mono_s = wpart + 16 * 32;             // [32]
    __half* a1f   = (__half*)(mono_s + 32);      // [32][ASTR]

    const int tid  = threadIdx.x;
    const int warp = tid >> 5;
    const int lane = tid & 31;
    const int b0   = blockIdx.x * ROWS;

    // ---- stage x_nm transposed: xs[i][r] ----
    for (int idx = tid; idx < ROWS * NMD; idx += 512) {
        int r = idx / NMD, i = idx % NMD;
        xs[i * RSTR + r] = X[(b0 + r) * INF + KM + i];
    }

    // ---- mono term: one (row, k) per thread, width-16 shuffle reduce ----
    {
        int r = tid >> 4;          // 0..31
        int k = tid & 15;
        const float scale = (float)(NT - 1) / (2.f * PMAXF);
        float x = __ldg(X + (b0 + r) * INF + k);
        const float* tk = g_tab + k * NT;
        float acc = 0.f;
#pragma unroll
        for (int s = 0; s < SQ; s++) {
            float t = (float)s * (1.f / (SQ - 1));
            float f = (x * t + PMAXF) * scale;
            f = fminf(fmaxf(f, 0.f), (float)(NT - 1) - 1e-3f);
            int i0 = (int)f;
            float fr = f - (float)i0;
            float g0 = tk[i0];
            float g1 = tk[i0 + 1];
            acc += fmaf(fr, g1 - g0, g0);
        }
        float part = acc * (1.f / SQ) * x * __ldg(wlin + k);
#pragma unroll
        for (int off = 8; off; off >>= 1)
            part += __shfl_down_sync(0xffffffffu, part, off, 16);
        if ((tid & 15) == 0) mono_s[r] = part;
    }
    __syncthreads();

    // ---- layer 1: thread owns col c = tid, all 32 rows; relu -> fp16 ----
    {
        const int c = tid;
        unsigned long long acc[16];
#pragma unroll
        for (int rp = 0; rp < 16; rp++) acc[rp] = 0ull;

        const float* wp = w1 + c;
#pragma unroll 4
        for (int i = 0; i < NMD; i++) {
            float wv = wp[i * NH];
            unsigned long long wd = pack2(wv, wv);
            const ulonglong2* ap = (const ulonglong2*)(xs + i * RSTR);
#pragma unroll
            for (int q = 0; q < 8; q++) {
                ulonglong2 a = ap[q];
                fma2(acc[2 * q],     a.x, wd);
                fma2(acc[2 * q + 1], a.y, wd);
            }
        }
        float bv = b1[c];
#pragma unroll
        for (int rp = 0; rp < 16; rp++) {
            float2 v = unpack2(acc[rp]);
            a1f[(2 * rp) * ASTR + c]     = __float2half_rn(fmaxf(v.x + bv, 0.f));
            a1f[(2 * rp + 1) * ASTR + c] = __float2half_rn(fmaxf(v.y + bv, 0.f));
        }
    }
    __syncthreads();

    // ---- layer 2: single-fp16 MMA, warp owns 32 cols x 32 rows ----
    {
        float acc[2][4][4];
#pragma unroll
        for (int m = 0; m < 2; m++)
#pragma unroll
            for (int nf = 0; nf < 4; nf++)
#pragma unroll
                for (int e = 0; e < 4; e++) acc[m][nf][e] = 0.f;

        const unsigned a1_u = smem_u32(a1f);
        const int arow  = lane & 15;
        const int acol8 = (lane >> 4) * 8;
        const uint4* bp = (const uint4*)w2f_frag;

        uint4 bq[2][2];
        {
            const uint4* p = bp + ((0 * 32 + lane) * 32 + warp * 2);
            bq[0][0] = p[0]; bq[0][1] = p[1];
        }

        for (int kf = 0; kf < 32; kf++) {
            int cur = kf & 1, nxt = cur ^ 1;
            if (kf < 31) {
                const uint4* p = bp + (((kf + 1) * 32 + lane) * 32 + warp * 2);
                bq[nxt][0] = p[0]; bq[nxt][1] = p[1];
            }
            unsigned a[2][4];
#pragma unroll
            for (int m = 0; m < 2; m++) {
                unsigned off = ((m * 16 + arow) * ASTR + kf * 16 + acol8) * 2;
                ldsm_x4(a[m][0], a[m][1], a[m][2], a[m][3], a1_u + off);
            }
            unsigned bfr[4][2] = {
                {bq[cur][0].x, bq[cur][0].y}, {bq[cur][0].z, bq[cur][0].w},
                {bq[cur][1].x, bq[cur][1].y}, {bq[cur][1].z, bq[cur][1].w}};
#pragma unroll
            for (int m = 0; m < 2; m++)
#pragma unroll
                for (int nf = 0; nf < 4; nf++)
                    mma_f16(acc[m][nf], a[m], bfr[nf]);
        }

        // epilogue: relu(acc + b2) . w3 -> per-row partials (32-col slice)
#pragma unroll
        for (int m = 0; m < 2; m++) {
            float p0 = 0.f, p1 = 0.f;
#pragma unroll
            for (int nf = 0; nf < 4; nf++) {
                int col = warp * 32 + nf * 8 + (lane & 3) * 2;
                float2 b2v = *(const float2*)(b2 + col);
                float2 w3v = *(const float2*)(w3 + col);
                p0 = fmaf(fmaxf(acc[m][nf][0] + b2v.x, 0.f), w3v.x, p0);
                p0 = fmaf(fmaxf(acc[m][nf][1] + b2v.y, 0.f), w3v.y, p0);
                p1 = fmaf(fmaxf(acc[m][nf][2] + b2v.x, 0.f), w3v.x, p1);
                p1 = fmaf(fmaxf(acc[m][nf][3] + b2v.y, 0.f), w3v.y, p1);
            }
            p0 += __shfl_xor_sync(0xffffffffu, p0, 1);
            p0 += __shfl_xor_sync(0xffffffffu, p0, 2);
            p1 += __shfl_xor_sync(0xffffffffu, p1, 1);
            p1 += __shfl_xor_sync(0xffffffffu, p1, 2);
            if ((lane & 3) == 0) {
                int r0 = m * 16 + (lane >> 2);
                wpart[warp * 32 + r0]     = p0;   // rows r0, r0+8
                wpart[warp * 32 + r0 + 8] = p1;
            }
        }
    }
    __syncthreads();

    // ---- final: sum 16 warp slices + bias + mono ----
    if (tid < ROWS) {
        float s = 0.f;
#pragma unroll
        for (int w = 0; w < 16; w++) s += wpart[w * 32 + tid];
        out[b0 + tid] = s + __ldg(b3) + mono_s[tid];
    }
}

// ---------------------------------------------------------------------------
extern "C" void kernel_launch(void* const* d_in, const int* in_sizes, int n_in,
                              void* d_out, int out_size)
{
    const float* x    = (const float*)d_in[0];
    const float* mw1  = (const float*)d_in[1];
    const float* mb1  = (const float*)d_in[2];
    const float* mw2  = (const float*)d_in[3];
    const float* mb2  = (const float*)d_in[4];
    const float* mw3  = (const float*)d_in[5];
    const float* mb3  = (const float*)d_in[6];
    const float* wlin = (const float*)d_in[7];
    const float* nw1  = (const float*)d_in[8];
    const float* nb1  = (const float*)d_in[9];
    const float* nw2  = (const float*)d_in[10];
    const float* nb2  = (const float*)d_in[11];
    const float* nw3  = (const float*)d_in[12];
    const float* nb3  = (const float*)d_in[13];
    float* out = (float*)d_out;

    // smem: xs + wpart + mono + a1f
    int smem = (NMD * RSTR + 16 * 32 + 32) * (int)sizeof(float)
             + ROWS * ASTR * (int)sizeof(__half);   // 42368 B
    cudaFuncSetAttribute(fused_kernel, cudaFuncAttributeMaxDynamicSharedMemorySize, smem);

    prep_kernel<<<NH * NH / 4 / 256, 256>>>(nw2);
    build_tab_kernel<<<KM * 8, 256>>>(mw1, mb1, mw2, mb2, mw3, mb3);
    fused_kernel<<<B_ / ROWS, 512, smem>>>(x, wlin, nw1, nb1, nb2, nw3, nb3, out);
}